// round 7
// baseline (speedup 1.0000x reference)
#include <cuda_runtime.h>
#include <cstdint>

// Problem constants (fixed shapes)
#define B_  2
#define N_  6
#define Q_  900
#define C_  256
#define H_  116
#define W_  200
#define HW_ (H_ * W_)       // 23200, divisible by 4
#define EPS_ 1e-5f
#define BQ_ (B_ * Q_)       // 1800

#define KSPLIT 4
#define KCHUNK (C_ / KSPLIT)   // 64

// Scratch (no dynamic allocation allowed)
__device__ float g_agg[BQ_ * C_];             // mean-aggregated features
__device__ float g_part[KSPLIT][BQ_ * C_];    // split-K partial GEMM results

// Uniform-index select from float4 (s is warp-uniform -> predicated SELs)
__device__ __forceinline__ float sel4(float4 f, int s) {
    float v = f.x;
    if (s == 1) v = f.y;
    else if (s == 2) v = f.z;
    else if (s == 3) v = f.w;
    return v;
}

// packed f32x2 fma: d = a*b + d elementwise on (lo,hi) pairs in 64-bit regs
__device__ __forceinline__ void ffma2(unsigned long long& d,
                                      unsigned long long a,
                                      unsigned long long b) {
    asm("fma.rn.f32x2 %0, %1, %2, %0;" : "+l"(d) : "l"(a), "l"(b));
}

// ---------------------------------------------------------------------------
// Fused kernel: projection + compaction + pipelined bilinear gather + mean
// one block per (b,q); 64 threads; 4 channels/thread (tid,+64,+128,+192);
// cameras compacted to a dense valid list; loads for camera i+1 issued
// before camera i is consumed (2-deep software pipeline).
// ---------------------------------------------------------------------------
__global__ __launch_bounds__(64) void gather_kernel(
    const float* __restrict__ feats,     // (B,N,C,H,W)
    const float* __restrict__ ref_pts,   // (B,Q,3)
    const float* __restrict__ lidar2img) // (B,N,4,4)
{
    __shared__ float4 sw_raw[N_];
    __shared__ int4   sb_raw[N_];
    __shared__ float4 swc[N_];   // compacted weights
    __shared__ int4   sbc[N_];   // compacted {base_top, base_bot, s0|(s1<<8), cam}
    __shared__ int    s_cnt;

    int bq  = blockIdx.x;       // 0..1799
    int b   = bq / Q_;
    int q   = bq % Q_;
    int tid = threadIdx.x;      // 0..63

    if (tid < N_) {
        int n = tid;
        const float* rp = ref_pts + ((size_t)b * Q_ + q) * 3;
        float px = rp[0], py = rp[1], pz = rp[2];

        const float* M = lidar2img + ((size_t)b * N_ + n) * 16;
        float xc = M[0]  * px + M[1]  * py + M[2]  * pz + M[3];
        float yc = M[4]  * px + M[5]  * py + M[6]  * pz + M[7];
        float zc = M[8]  * px + M[9]  * py + M[10] * pz + M[11];

        float denom = fabsf(zc) + EPS_;
        float x2d = xc / denom;
        float y2d = yc / denom;

        float gx = x2d / (float)(W_ - 1) * 2.0f - 1.0f;
        float gy = y2d / (float)(H_ - 1) * 2.0f - 1.0f;

        bool front  = zc > EPS_;
        bool in_img = fmaxf(fabsf(gx), fabsf(gy)) <= 1.0f;
        int  valid  = (front && in_img) ? 1 : 0;
        float vv    = valid ? (1.0f / (float)N_) : 0.0f;

        float x = ((gx + 1.0f) * (float)W_ - 1.0f) * 0.5f;
        float y = ((gy + 1.0f) * (float)H_ - 1.0f) * 0.5f;
        x = fminf(fmaxf(x, -100.0f), (float)(W_ + 100));
        y = fminf(fmaxf(y, -100.0f), (float)(H_ + 100));

        float x0f = floorf(x), y0f = floorf(y);
        float wx = x - x0f, wy = y - y0f;
        int x0 = (int)x0f, y0 = (int)y0f;
        int x1 = x0 + 1,   y1 = y0 + 1;

        float v00 = (x0 >= 0 && x0 < W_ && y0 >= 0 && y0 < H_) ? 1.0f : 0.0f;
        float v10 = (x1 >= 0 && x1 < W_ && y0 >= 0 && y0 < H_) ? 1.0f : 0.0f;
        float v01 = (x0 >= 0 && x0 < W_ && y1 >= 0 && y1 < H_) ? 1.0f : 0.0f;
        float v11 = (x1 >= 0 && x1 < W_ && y1 >= 0 && y1 < H_) ? 1.0f : 0.0f;

        float4 w;
        w.x = (1.0f - wx) * (1.0f - wy) * v00 * vv;
        w.y = wx          * (1.0f - wy) * v10 * vv;
        w.z = (1.0f - wx) * wy          * v01 * vv;
        w.w = wx          * wy          * v11 * vv;

        int cx0 = min(max(x0, 0), W_ - 1);
        int cx1 = min(max(x1, 0), W_ - 1);
        int cy0 = min(max(y0, 0), H_ - 1);
        int cy1 = min(max(y1, 0), H_ - 1);

        int i0 = cy0 * W_ + cx0;
        int i1 = cy0 * W_ + cx1;
        int j0 = cy1 * W_ + cx0;

        int base_t = i0 & ~3;
        int s0 = i0 - base_t;
        int s1 = i1 - base_t;
        int base_b = j0 - s0;

        sw_raw[n] = w;
        sb_raw[n] = make_int4(base_t, base_b, s0 | (s1 << 8), valid);
    }
    __syncthreads();
    if (tid == 0) {
        int cnt = 0;
        #pragma unroll
        for (int n = 0; n < N_; n++) {
            int4 r = sb_raw[n];
            if (r.w) {
                swc[cnt] = sw_raw[n];
                sbc[cnt] = make_int4(r.x, r.y, r.z, n);
                cnt++;
            }
        }
        s_cnt = cnt;
    }
    __syncthreads();

    int V = s_cnt;
    float acc0 = 0.0f, acc1 = 0.0f, acc2 = 0.0f, acc3 = 0.0f;

    const float* base = feats + (size_t)(b * N_ * C_) * HW_ + (size_t)tid * HW_;

    // pipeline registers (current camera)
    float4 w;  int4 ib;
    float4 t0, bt0, t1, bt1, t2, bt2, t3, bt3;

    if (V > 0) {
        w  = swc[0];
        ib = sbc[0];
        const float* p0 = base + (size_t)(ib.w * C_) * HW_;
        const float* p1 = p0 + (size_t)64  * HW_;
        const float* p2 = p0 + (size_t)128 * HW_;
        const float* p3 = p0 + (size_t)192 * HW_;
        t0  = *reinterpret_cast<const float4*>(p0 + ib.x);
        bt0 = *reinterpret_cast<const float4*>(p0 + ib.y);
        t1  = *reinterpret_cast<const float4*>(p1 + ib.x);
        bt1 = *reinterpret_cast<const float4*>(p1 + ib.y);
        t2  = *reinterpret_cast<const float4*>(p2 + ib.x);
        bt2 = *reinterpret_cast<const float4*>(p2 + ib.y);
        t3  = *reinterpret_cast<const float4*>(p3 + ib.x);
        bt3 = *reinterpret_cast<const float4*>(p3 + ib.y);
    }

    for (int i = 0; i < V; i++) {
        // prefetch camera i+1 (independent of current consume)
        float4 nw;  int4 nib;
        float4 nt0, nbt0, nt1, nbt1, nt2, nbt2, nt3, nbt3;
        if (i + 1 < V) {
            nw  = swc[i + 1];
            nib = sbc[i + 1];
            const float* p0 = base + (size_t)(nib.w * C_) * HW_;
            const float* p1 = p0 + (size_t)64  * HW_;
            const float* p2 = p0 + (size_t)128 * HW_;
            const float* p3 = p0 + (size_t)192 * HW_;
            nt0  = *reinterpret_cast<const float4*>(p0 + nib.x);
            nbt0 = *reinterpret_cast<const float4*>(p0 + nib.y);
            nt1  = *reinterpret_cast<const float4*>(p1 + nib.x);
            nbt1 = *reinterpret_cast<const float4*>(p1 + nib.y);
            nt2  = *reinterpret_cast<const float4*>(p2 + nib.x);
            nbt2 = *reinterpret_cast<const float4*>(p2 + nib.y);
            nt3  = *reinterpret_cast<const float4*>(p3 + nib.x);
            nbt3 = *reinterpret_cast<const float4*>(p3 + nib.y);
        }

        // consume camera i
        {
            int s0 = ib.z & 0xff;
            int s1 = ib.z >> 8;
            float vt0a = sel4(t0, s0),  vb0a = sel4(bt0, s0);
            float vt0b = sel4(t1, s0),  vb0b = sel4(bt1, s0);
            float vt0c = sel4(t2, s0),  vb0c = sel4(bt2, s0);
            float vt0d = sel4(t3, s0),  vb0d = sel4(bt3, s0);
            float vt1a, vb1a, vt1b, vb1b, vt1c, vb1c, vt1d, vb1d;
            if (s1 < 4) {               // uniform branch (75% taken)
                vt1a = sel4(t0, s1);  vb1a = sel4(bt0, s1);
                vt1b = sel4(t1, s1);  vb1b = sel4(bt1, s1);
                vt1c = sel4(t2, s1);  vb1c = sel4(bt2, s1);
                vt1d = sel4(t3, s1);  vb1d = sel4(bt3, s1);
            } else {                    // right pixel spills into next float4
                const float* p0 = base + (size_t)(ib.w * C_) * HW_;
                const float* p1 = p0 + (size_t)64  * HW_;
                const float* p2 = p0 + (size_t)128 * HW_;
                const float* p3 = p0 + (size_t)192 * HW_;
                vt1a = __ldg(p0 + ib.x + 4);  vb1a = __ldg(p0 + ib.y + 4);
                vt1b = __ldg(p1 + ib.x + 4);  vb1b = __ldg(p1 + ib.y + 4);
                vt1c = __ldg(p2 + ib.x + 4);  vb1c = __ldg(p2 + ib.y + 4);
                vt1d = __ldg(p3 + ib.x + 4);  vb1d = __ldg(p3 + ib.y + 4);
            }
            acc0 = fmaf(w.x, vt0a, acc0);
            acc0 = fmaf(w.y, vt1a, acc0);
            acc0 = fmaf(w.z, vb0a, acc0);
            acc0 = fmaf(w.w, vb1a, acc0);
            acc1 = fmaf(w.x, vt0b, acc1);
            acc1 = fmaf(w.y, vt1b, acc1);
            acc1 = fmaf(w.z, vb0b, acc1);
            acc1 = fmaf(w.w, vb1b, acc1);
            acc2 = fmaf(w.x, vt0c, acc2);
            acc2 = fmaf(w.y, vt1c, acc2);
            acc2 = fmaf(w.z, vb0c, acc2);
            acc2 = fmaf(w.w, vb1c, acc2);
            acc3 = fmaf(w.x, vt0d, acc3);
            acc3 = fmaf(w.y, vt1d, acc3);
            acc3 = fmaf(w.z, vb0d, acc3);
            acc3 = fmaf(w.w, vb1d, acc3);
        }

        // rotate pipeline registers
        w = nw;  ib = nib;
        t0 = nt0;  bt0 = nbt0;
        t1 = nt1;  bt1 = nbt1;
        t2 = nt2;  bt2 = nbt2;
        t3 = nt3;  bt3 = nbt3;
    }

    float* outp = &g_agg[(size_t)bq * C_ + tid];
    outp[0]   = acc0;
    outp[64]  = acc1;
    outp[128] = acc2;
    outp[192] = acc3;
}

// ---------------------------------------------------------------------------
// Split-K GEMM: part[z] = agg[:, z*64:(z+1)*64] @ W^T[z*64:(z+1)*64, :]
// (unchanged)
// ---------------------------------------------------------------------------
#define BM 64
#define BN 64
#define BK 16
#define NT (KCHUNK / BK)   // 4 tiles per k-chunk

__global__ __launch_bounds__(256) void gemm_kernel(const float* __restrict__ Wm)
{
    __shared__ float AsDup[2][BK][BM * 2];   // 16 KB: each A value stored twice
    __shared__ float Bs[2][BK][BN];          // 8 KB

    const int M = BQ_;
    int t  = threadIdx.x;
    int tm = t / 16;
    int tn = t % 16;

    int bM = blockIdx.x * BM;
    int bN = blockIdx.y * BN;
    int z  = blockIdx.z;
    int kb = z * KCHUNK;

    int lrow = t >> 2;
    int lk   = (t & 3) * 4;

    const float* Aptr = &g_agg[(size_t)(bM + lrow) * C_ + kb + lk];
    const float* Bptr = &Wm[(size_t)(bN + lrow) * C_ + kb + lk];
    bool arow_ok = (bM + lrow) < M;

    unsigned long long acc2[4][2];
#pragma unroll
    for (int i = 0; i < 4; i++) { acc2[i][0] = 0ull; acc2[i][1] = 0ull; }

    float4 av = make_float4(0.f, 0.f, 0.f, 0.f);
    if (arow_ok) av = *reinterpret_cast<const float4*>(Aptr);
    float4 bv = *reinterpret_cast<const float4*>(Bptr);
    {
        float* ad = &AsDup[0][0][0];
        *reinterpret_cast<float2*>(&ad[(lk + 0) * (BM * 2) + lrow * 2]) = make_float2(av.x, av.x);
        *reinterpret_cast<float2*>(&ad[(lk + 1) * (BM * 2) + lrow * 2]) = make_float2(av.y, av.y);
        *reinterpret_cast<float2*>(&ad[(lk + 2) * (BM * 2) + lrow * 2]) = make_float2(av.z, av.z);
        *reinterpret_cast<float2*>(&ad[(lk + 3) * (BM * 2) + lrow * 2]) = make_float2(av.w, av.w);
        Bs[0][lk + 0][lrow] = bv.x;
        Bs[0][lk + 1][lrow] = bv.y;
        Bs[0][lk + 2][lrow] = bv.z;
        Bs[0][lk + 3][lrow] = bv.w;
    }
    __syncthreads();

    for (int tile = 0; tile < NT; tile++) {
        int cur = tile & 1;
        int nxt = cur ^ 1;

        if (tile + 1 < NT) {
            av = make_float4(0.f, 0.f, 0.f, 0.f);
            if (arow_ok) av = *reinterpret_cast<const float4*>(Aptr + (tile + 1) * BK);
            bv = *reinterpret_cast<const float4*>(Bptr + (tile + 1) * BK);
        }

        ulonglong2 fa01[2], fa23[2], fb[2];
        {
            const ulonglong2* ap = reinterpret_cast<const ulonglong2*>(&AsDup[cur][0][tm * 8]);
            fa01[0] = ap[0];
            fa23[0] = ap[1];
            fb[0]   = *reinterpret_cast<const ulonglong2*>(&Bs[cur][0][tn * 4]);
        }
#pragma unroll
        for (int kk = 0; kk < BK; kk++) {
            int c = kk & 1, nx = c ^ 1;
            if (kk + 1 < BK) {
                const ulonglong2* ap = reinterpret_cast<const ulonglong2*>(&AsDup[cur][kk + 1][tm * 8]);
                fa01[nx] = ap[0];
                fa23[nx] = ap[1];
                fb[nx]   = *reinterpret_cast<const ulonglong2*>(&Bs[cur][kk + 1][tn * 4]);
            }
            ffma2(acc2[0][0], fa01[c].x, fb[c].x);
            ffma2(acc2[0][1], fa01[c].x, fb[c].y);
            ffma2(acc2[1][0], fa01[c].y, fb[c].x);
            ffma2(acc2[1][1], fa01[c].y, fb[c].y);
            ffma2(acc2[2][0], fa23[c].x, fb[c].x);
            ffma2(acc2[2][1], fa23[c].x, fb[c].y);
            ffma2(acc2[3][0], fa23[c].y, fb[c].x);
            ffma2(acc2[3][1], fa23[c].y, fb[c].y);
        }

        if (tile + 1 < NT) {
            float* ad = &AsDup[nxt][0][0];
            *reinterpret_cast<float2*>(&ad[(lk + 0) * (BM * 2) + lrow * 2]) = make_float2(av.x, av.x);
            *reinterpret_cast<float2*>(&ad[(lk + 1) * (BM * 2) + lrow * 2]) = make_float2(av.y, av.y);
            *reinterpret_cast<float2*>(&ad[(lk + 2) * (BM * 2) + lrow * 2]) = make_float2(av.z, av.z);
            *reinterpret_cast<float2*>(&ad[(lk + 3) * (BM * 2) + lrow * 2]) = make_float2(av.w, av.w);
            Bs[nxt][lk + 0][lrow] = bv.x;
            Bs[nxt][lk + 1][lrow] = bv.y;
            Bs[nxt][lk + 2][lrow] = bv.z;
            Bs[nxt][lk + 3][lrow] = bv.w;
            __syncthreads();
        }
    }

    float* pout = &g_part[z][0];
#pragma unroll
    for (int i = 0; i < 4; i++) {
        int gm = bM + tm * 4 + i;
        if (gm >= M) continue;
        float2 lo = *reinterpret_cast<float2*>(&acc2[i][0]);
        float2 hi = *reinterpret_cast<float2*>(&acc2[i][1]);
        *reinterpret_cast<float4*>(&pout[(size_t)gm * C_ + bN + tn * 4]) =
            make_float4(lo.x, lo.y, hi.x, hi.y);
    }
}

// ---------------------------------------------------------------------------
// fixup: out = sum_z part[z] + bias    (fixed order -> deterministic)
// ---------------------------------------------------------------------------
__global__ __launch_bounds__(256) void fixup_kernel(const float* __restrict__ bias,
                                                    float* __restrict__ out)
{
    int i = blockIdx.x * blockDim.x + threadIdx.x;   // float4 index
    const int NV = BQ_ * C_ / 4;                     // 115200
    if (i >= NV) return;
    int e = i * 4;
    float4 s = *reinterpret_cast<const float4*>(&g_part[0][e]);
#pragma unroll
    for (int z = 1; z < KSPLIT; z++) {
        float4 p = *reinterpret_cast<const float4*>(&g_part[z][e]);
        s.x += p.x; s.y += p.y; s.z += p.z; s.w += p.w;
    }
    float4 bb = *reinterpret_cast<const float4*>(&bias[e & (C_ - 1)]);
    s.x += bb.x; s.y += bb.y; s.z += bb.z; s.w += bb.w;
    *reinterpret_cast<float4*>(&out[e]) = s;
}

// ---------------------------------------------------------------------------
// launch
// inputs: 0=query (unused), 1=reference_points, 2=image_features,
//         3=lidar2img, 4=W_out, 5=b_out; output float32 (B,Q,C)
// ---------------------------------------------------------------------------
extern "C" void kernel_launch(void* const* d_in, const int* in_sizes, int n_in,
                              void* d_out, int out_size)
{
    const float* ref_pts   = (const float*)d_in[1];
    const float* feats     = (const float*)d_in[2];
    const float* lidar2img = (const float*)d_in[3];
    const float* Wm        = (const float*)d_in[4];
    const float* bias      = (const float*)d_in[5];
    float* out = (float*)d_out;

    gather_kernel<<<BQ_, 64>>>(feats, ref_pts, lidar2img);
    dim3 gg((BQ_ + BM - 1) / BM, C_ / BN, KSPLIT);
    gemm_kernel<<<gg, 256>>>(Wm);
    fixup_kernel<<<(BQ_ * C_ / 4 + 255) / 256, 256>>>(bias, out);
}

// round 8
// speedup vs baseline: 1.0769x; 1.0769x over previous
#include <cuda_runtime.h>
#include <cstdint>

// Problem constants (fixed shapes)
#define B_  2
#define N_  6
#define Q_  900
#define C_  256
#define H_  116
#define W_  200
#define HW_ (H_ * W_)       // 23200, divisible by 4
#define EPS_ 1e-5f
#define BQ_ (B_ * Q_)       // 1800

#define KSPLIT 4
#define KCHUNK (C_ / KSPLIT)   // 64
#define NHALF 2                // camera-loop split factor
#define CAMS_PER_HALF (N_ / NHALF)   // 3

// Scratch (no dynamic allocation allowed)
__device__ float g_aggp[NHALF][BQ_ * C_];     // partial camera sums (halves)
__device__ float g_part[KSPLIT][BQ_ * C_];    // split-K partial GEMM results

// Uniform-index select from float4 (s is warp-uniform -> predicated SELs)
__device__ __forceinline__ float sel4(float4 f, int s) {
    float v = f.x;
    if (s == 1) v = f.y;
    else if (s == 2) v = f.z;
    else if (s == 3) v = f.w;
    return v;
}

// packed f32x2 fma: d = a*b + d elementwise on (lo,hi) pairs in 64-bit regs
__device__ __forceinline__ void ffma2(unsigned long long& d,
                                      unsigned long long a,
                                      unsigned long long b) {
    asm("fma.rn.f32x2 %0, %1, %2, %0;" : "+l"(d) : "l"(a), "l"(b));
}

// ---------------------------------------------------------------------------
// Fused kernel: projection (threads 0..5) + bilinear gather over HALF the
// cameras. blockIdx.x = bq * NHALF + half. 64 threads; 4 channels/thread.
// Partial sums written to g_aggp[half]; summed during GEMM A-tile load.
// ---------------------------------------------------------------------------
__global__ void __launch_bounds__(64, 16) gather_kernel(
    const float* __restrict__ feats,     // (B,N,C,H,W)
    const float* __restrict__ ref_pts,   // (B,Q,3)
    const float* __restrict__ lidar2img) // (B,N,4,4)
{
    __shared__ float4 sw[CAMS_PER_HALF];
    __shared__ int4   sb[CAMS_PER_HALF];

    int blk  = blockIdx.x;            // 0..3599
    int half = blk & (NHALF - 1);
    int bq   = blk >> 1;              // 0..1799
    int b    = bq / Q_;
    int q    = bq % Q_;
    int tid  = threadIdx.x;           // 0..63

    if (tid < CAMS_PER_HALF) {
        int n = half * CAMS_PER_HALF + tid;
        const float* rp = ref_pts + ((size_t)b * Q_ + q) * 3;
        float px = rp[0], py = rp[1], pz = rp[2];

        const float* M = lidar2img + ((size_t)b * N_ + n) * 16;
        float xc = M[0]  * px + M[1]  * py + M[2]  * pz + M[3];
        float yc = M[4]  * px + M[5]  * py + M[6]  * pz + M[7];
        float zc = M[8]  * px + M[9]  * py + M[10] * pz + M[11];

        float denom = fabsf(zc) + EPS_;
        float x2d = xc / denom;
        float y2d = yc / denom;

        float gx = x2d / (float)(W_ - 1) * 2.0f - 1.0f;
        float gy = y2d / (float)(H_ - 1) * 2.0f - 1.0f;

        bool front  = zc > EPS_;
        bool in_img = fmaxf(fabsf(gx), fabsf(gy)) <= 1.0f;
        int  valid  = (front && in_img) ? 1 : 0;
        float vv    = valid ? (1.0f / (float)N_) : 0.0f;

        float x = ((gx + 1.0f) * (float)W_ - 1.0f) * 0.5f;
        float y = ((gy + 1.0f) * (float)H_ - 1.0f) * 0.5f;
        x = fminf(fmaxf(x, -100.0f), (float)(W_ + 100));
        y = fminf(fmaxf(y, -100.0f), (float)(H_ + 100));

        float x0f = floorf(x), y0f = floorf(y);
        float wx = x - x0f, wy = y - y0f;
        int x0 = (int)x0f, y0 = (int)y0f;
        int x1 = x0 + 1,   y1 = y0 + 1;

        float v00 = (x0 >= 0 && x0 < W_ && y0 >= 0 && y0 < H_) ? 1.0f : 0.0f;
        float v10 = (x1 >= 0 && x1 < W_ && y0 >= 0 && y0 < H_) ? 1.0f : 0.0f;
        float v01 = (x0 >= 0 && x0 < W_ && y1 >= 0 && y1 < H_) ? 1.0f : 0.0f;
        float v11 = (x1 >= 0 && x1 < W_ && y1 >= 0 && y1 < H_) ? 1.0f : 0.0f;

        float4 w;
        w.x = (1.0f - wx) * (1.0f - wy) * v00 * vv;
        w.y = wx          * (1.0f - wy) * v10 * vv;
        w.z = (1.0f - wx) * wy          * v01 * vv;
        w.w = wx          * wy          * v11 * vv;

        int cx0 = min(max(x0, 0), W_ - 1);
        int cx1 = min(max(x1, 0), W_ - 1);
        int cy0 = min(max(y0, 0), H_ - 1);
        int cy1 = min(max(y1, 0), H_ - 1);

        int i0 = cy0 * W_ + cx0;
        int i1 = cy0 * W_ + cx1;
        int j0 = cy1 * W_ + cx0;

        int base_t = i0 & ~3;
        int s0 = i0 - base_t;
        int s1 = i1 - base_t;
        int base_b = j0 - s0;

        sw[tid] = w;
        sb[tid] = make_int4(base_t, base_b, s0 | (s1 << 8), valid);
    }
    __syncthreads();

    float acc0 = 0.0f;   // channel tid
    float acc1 = 0.0f;   // channel tid + 64
    float acc2 = 0.0f;   // channel tid + 128
    float acc3 = 0.0f;   // channel tid + 192

    const float* cambase = feats
        + (size_t)((b * N_ + half * CAMS_PER_HALF) * C_ + tid) * HW_;

#pragma unroll
    for (int k = 0; k < CAMS_PER_HALF; k++) {
        int4 ib = sb[k];
        if (!ib.w) continue;            // uniform branch: camera invalid
        float4 w = sw[k];
        const float* p0 = cambase + (size_t)(k * C_) * HW_;
        const float* p1 = p0 + (size_t)64  * HW_;
        const float* p2 = p0 + (size_t)128 * HW_;
        const float* p3 = p0 + (size_t)192 * HW_;

        // issue all 8 independent 16B loads before consuming
        float4 t0 = *reinterpret_cast<const float4*>(p0 + ib.x);
        float4 b0v = *reinterpret_cast<const float4*>(p0 + ib.y);
        float4 t1 = *reinterpret_cast<const float4*>(p1 + ib.x);
        float4 b1v = *reinterpret_cast<const float4*>(p1 + ib.y);
        float4 t2 = *reinterpret_cast<const float4*>(p2 + ib.x);
        float4 b2v = *reinterpret_cast<const float4*>(p2 + ib.y);
        float4 t3 = *reinterpret_cast<const float4*>(p3 + ib.x);
        float4 b3v = *reinterpret_cast<const float4*>(p3 + ib.y);

        int s0 = ib.z & 0xff;
        int s1 = ib.z >> 8;

        float vt0a = sel4(t0, s0), vb0a = sel4(b0v, s0);
        float vt0b = sel4(t1, s0), vb0b = sel4(b1v, s0);
        float vt0c = sel4(t2, s0), vb0c = sel4(b2v, s0);
        float vt0d = sel4(t3, s0), vb0d = sel4(b3v, s0);
        float vt1a, vb1a, vt1b, vb1b, vt1c, vb1c, vt1d, vb1d;
        if (s1 < 4) {                   // uniform branch (75% taken)
            vt1a = sel4(t0, s1);  vb1a = sel4(b0v, s1);
            vt1b = sel4(t1, s1);  vb1b = sel4(b1v, s1);
            vt1c = sel4(t2, s1);  vb1c = sel4(b2v, s1);
            vt1d = sel4(t3, s1);  vb1d = sel4(b3v, s1);
        } else {                        // right pixel spills into next float4
            vt1a = __ldg(p0 + ib.x + 4);  vb1a = __ldg(p0 + ib.y + 4);
            vt1b = __ldg(p1 + ib.x + 4);  vb1b = __ldg(p1 + ib.y + 4);
            vt1c = __ldg(p2 + ib.x + 4);  vb1c = __ldg(p2 + ib.y + 4);
            vt1d = __ldg(p3 + ib.x + 4);  vb1d = __ldg(p3 + ib.y + 4);
        }
        acc0 = fmaf(w.x, vt0a, acc0);
        acc0 = fmaf(w.y, vt1a, acc0);
        acc0 = fmaf(w.z, vb0a, acc0);
        acc0 = fmaf(w.w, vb1a, acc0);
        acc1 = fmaf(w.x, vt0b, acc1);
        acc1 = fmaf(w.y, vt1b, acc1);
        acc1 = fmaf(w.z, vb0b, acc1);
        acc1 = fmaf(w.w, vb1b, acc1);
        acc2 = fmaf(w.x, vt0c, acc2);
        acc2 = fmaf(w.y, vt1c, acc2);
        acc2 = fmaf(w.z, vb0c, acc2);
        acc2 = fmaf(w.w, vb1c, acc2);
        acc3 = fmaf(w.x, vt0d, acc3);
        acc3 = fmaf(w.y, vt1d, acc3);
        acc3 = fmaf(w.z, vb0d, acc3);
        acc3 = fmaf(w.w, vb1d, acc3);
    }
    float* outp = &g_aggp[half][(size_t)bq * C_ + tid];
    outp[0]   = acc0;
    outp[64]  = acc1;
    outp[128] = acc2;
    outp[192] = acc3;
}

// ---------------------------------------------------------------------------
// Split-K GEMM: part[z] = (aggp0+aggp1)[:, kchunk] @ W^T[kchunk, :]
// A halves summed during the tile load.
// ---------------------------------------------------------------------------
#define BM 64
#define BN 64
#define BK 16
#define NT (KCHUNK / BK)   // 4 tiles per k-chunk

__global__ __launch_bounds__(256) void gemm_kernel(const float* __restrict__ Wm)
{
    __shared__ float AsDup[2][BK][BM * 2];   // 16 KB: each A value stored twice
    __shared__ float Bs[2][BK][BN];          // 8 KB

    const int M = BQ_;
    int t  = threadIdx.x;
    int tm = t / 16;
    int tn = t % 16;

    int bM = blockIdx.x * BM;
    int bN = blockIdx.y * BN;
    int z  = blockIdx.z;
    int kb = z * KCHUNK;

    int lrow = t >> 2;
    int lk   = (t & 3) * 4;

    size_t aoff = (size_t)(bM + lrow) * C_ + kb + lk;
    const float* Aptr0 = &g_aggp[0][aoff];
    const float* Aptr1 = &g_aggp[1][aoff];
    const float* Bptr  = &Wm[(size_t)(bN + lrow) * C_ + kb + lk];
    bool arow_ok = (bM + lrow) < M;

    unsigned long long acc2[4][2];
#pragma unroll
    for (int i = 0; i < 4; i++) { acc2[i][0] = 0ull; acc2[i][1] = 0ull; }

    float4 av = make_float4(0.f, 0.f, 0.f, 0.f);
    if (arow_ok) {
        float4 a0 = *reinterpret_cast<const float4*>(Aptr0);
        float4 a1 = *reinterpret_cast<const float4*>(Aptr1);
        av = make_float4(a0.x + a1.x, a0.y + a1.y, a0.z + a1.z, a0.w + a1.w);
    }
    float4 bv = *reinterpret_cast<const float4*>(Bptr);
    {
        float* ad = &AsDup[0][0][0];
        *reinterpret_cast<float2*>(&ad[(lk + 0) * (BM * 2) + lrow * 2]) = make_float2(av.x, av.x);
        *reinterpret_cast<float2*>(&ad[(lk + 1) * (BM * 2) + lrow * 2]) = make_float2(av.y, av.y);
        *reinterpret_cast<float2*>(&ad[(lk + 2) * (BM * 2) + lrow * 2]) = make_float2(av.z, av.z);
        *reinterpret_cast<float2*>(&ad[(lk + 3) * (BM * 2) + lrow * 2]) = make_float2(av.w, av.w);
        Bs[0][lk + 0][lrow] = bv.x;
        Bs[0][lk + 1][lrow] = bv.y;
        Bs[0][lk + 2][lrow] = bv.z;
        Bs[0][lk + 3][lrow] = bv.w;
    }
    __syncthreads();

    for (int tile = 0; tile < NT; tile++) {
        int cur = tile & 1;
        int nxt = cur ^ 1;

        if (tile + 1 < NT) {
            av = make_float4(0.f, 0.f, 0.f, 0.f);
            if (arow_ok) {
                float4 a0 = *reinterpret_cast<const float4*>(Aptr0 + (tile + 1) * BK);
                float4 a1 = *reinterpret_cast<const float4*>(Aptr1 + (tile + 1) * BK);
                av = make_float4(a0.x + a1.x, a0.y + a1.y, a0.z + a1.z, a0.w + a1.w);
            }
            bv = *reinterpret_cast<const float4*>(Bptr + (tile + 1) * BK);
        }

        ulonglong2 fa01[2], fa23[2], fb[2];
        {
            const ulonglong2* ap = reinterpret_cast<const ulonglong2*>(&AsDup[cur][0][tm * 8]);
            fa01[0] = ap[0];
            fa23[0] = ap[1];
            fb[0]   = *reinterpret_cast<const ulonglong2*>(&Bs[cur][0][tn * 4]);
        }
#pragma unroll
        for (int kk = 0; kk < BK; kk++) {
            int c = kk & 1, nx = c ^ 1;
            if (kk + 1 < BK) {
                const ulonglong2* ap = reinterpret_cast<const ulonglong2*>(&AsDup[cur][kk + 1][tm * 8]);
                fa01[nx] = ap[0];
                fa23[nx] = ap[1];
                fb[nx]   = *reinterpret_cast<const ulonglong2*>(&Bs[cur][kk + 1][tn * 4]);
            }
            ffma2(acc2[0][0], fa01[c].x, fb[c].x);
            ffma2(acc2[0][1], fa01[c].x, fb[c].y);
            ffma2(acc2[1][0], fa01[c].y, fb[c].x);
            ffma2(acc2[1][1], fa01[c].y, fb[c].y);
            ffma2(acc2[2][0], fa23[c].x, fb[c].x);
            ffma2(acc2[2][1], fa23[c].x, fb[c].y);
            ffma2(acc2[3][0], fa23[c].y, fb[c].x);
            ffma2(acc2[3][1], fa23[c].y, fb[c].y);
        }

        if (tile + 1 < NT) {
            float* ad = &AsDup[nxt][0][0];
            *reinterpret_cast<float2*>(&ad[(lk + 0) * (BM * 2) + lrow * 2]) = make_float2(av.x, av.x);
            *reinterpret_cast<float2*>(&ad[(lk + 1) * (BM * 2) + lrow * 2]) = make_float2(av.y, av.y);
            *reinterpret_cast<float2*>(&ad[(lk + 2) * (BM * 2) + lrow * 2]) = make_float2(av.z, av.z);
            *reinterpret_cast<float2*>(&ad[(lk + 3) * (BM * 2) + lrow * 2]) = make_float2(av.w, av.w);
            Bs[nxt][lk + 0][lrow] = bv.x;
            Bs[nxt][lk + 1][lrow] = bv.y;
            Bs[nxt][lk + 2][lrow] = bv.z;
            Bs[nxt][lk + 3][lrow] = bv.w;
            __syncthreads();
        }
    }

    float* pout = &g_part[z][0];
#pragma unroll
    for (int i = 0; i < 4; i++) {
        int gm = bM + tm * 4 + i;
        if (gm >= M) continue;
        float2 lo = *reinterpret_cast<float2*>(&acc2[i][0]);
        float2 hi = *reinterpret_cast<float2*>(&acc2[i][1]);
        *reinterpret_cast<float4*>(&pout[(size_t)gm * C_ + bN + tn * 4]) =
            make_float4(lo.x, lo.y, hi.x, hi.y);
    }
}

// ---------------------------------------------------------------------------
// fixup: out = sum_z part[z] + bias    (fixed order -> deterministic)
// ---------------------------------------------------------------------------
__global__ __launch_bounds__(256) void fixup_kernel(const float* __restrict__ bias,
                                                    float* __restrict__ out)
{
    int i = blockIdx.x * blockDim.x + threadIdx.x;   // float4 index
    const int NV = BQ_ * C_ / 4;                     // 115200
    if (i >= NV) return;
    int e = i * 4;
    float4 s = *reinterpret_cast<const float4*>(&g_part[0][e]);
#pragma unroll
    for (int z = 1; z < KSPLIT; z++) {
        float4 p = *reinterpret_cast<const float4*>(&g_part[z][e]);
        s.x += p.x; s.y += p.y; s.z += p.z; s.w += p.w;
    }
    float4 bb = *reinterpret_cast<const float4*>(&bias[e & (C_ - 1)]);
    s.x += bb.x; s.y += bb.y; s.z += bb.z; s.w += bb.w;
    *reinterpret_cast<float4*>(&out[e]) = s;
}

// ---------------------------------------------------------------------------
// launch
// inputs: 0=query (unused), 1=reference_points, 2=image_features,
//         3=lidar2img, 4=W_out, 5=b_out; output float32 (B,Q,C)
// ---------------------------------------------------------------------------
extern "C" void kernel_launch(void* const* d_in, const int* in_sizes, int n_in,
                              void* d_out, int out_size)
{
    const float* ref_pts   = (const float*)d_in[1];
    const float* feats     = (const float*)d_in[2];
    const float* lidar2img = (const float*)d_in[3];
    const float* Wm        = (const float*)d_in[4];
    const float* bias      = (const float*)d_in[5];
    float* out = (float*)d_out;

    gather_kernel<<<BQ_ * NHALF, 64>>>(feats, ref_pts, lidar2img);
    dim3 gg((BQ_ + BM - 1) / BM, C_ / BN, KSPLIT);
    gemm_kernel<<<gg, 256>>>(Wm);
    fixup_kernel<<<(BQ_ * C_ / 4 + 255) / 256, 256>>>(bias, out);
}

// round 9
// speedup vs baseline: 1.1313x; 1.0505x over previous
#include <cuda_runtime.h>
#include <cstdint>

// Problem constants (fixed shapes)
#define B_  2
#define N_  6
#define Q_  900
#define C_  256
#define H_  116
#define W_  200
#define HW_ (H_ * W_)       // 23200, divisible by 4
#define EPS_ 1e-5f
#define BQ_ (B_ * Q_)       // 1800

#define KSPLIT 8
#define KCHUNK (C_ / KSPLIT)   // 32

// Scratch (no dynamic allocation allowed)
__device__ float g_agg[BQ_ * C_];             // mean-aggregated features
__device__ float g_part[KSPLIT][BQ_ * C_];    // split-K partial GEMM results

// Uniform-index select from float4 (s is warp-uniform -> predicated SELs)
__device__ __forceinline__ float sel4(float4 f, int s) {
    float v = f.x;
    if (s == 1) v = f.y;
    else if (s == 2) v = f.z;
    else if (s == 3) v = f.w;
    return v;
}

// packed f32x2 fma: d = a*b + d elementwise on (lo,hi) pairs in 64-bit regs
__device__ __forceinline__ void ffma2(unsigned long long& d,
                                      unsigned long long a,
                                      unsigned long long b) {
    asm("fma.rn.f32x2 %0, %1, %2, %0;" : "+l"(d) : "l"(a), "l"(b));
}

// ---------------------------------------------------------------------------
// Fused kernel: projection (threads 0..5) + bilinear gather + camera mean
// one block per (b,q); 64 threads; 4 channels/thread (tid,+64,+128,+192)
// [identical to the R6 best-known gather]
// ---------------------------------------------------------------------------
__global__ __launch_bounds__(64) void gather_kernel(
    const float* __restrict__ feats,     // (B,N,C,H,W)
    const float* __restrict__ ref_pts,   // (B,Q,3)
    const float* __restrict__ lidar2img) // (B,N,4,4)
{
    __shared__ float4 sw[N_];   // weights: (wl_top, wr_top, wl_bot, wr_bot) * valid/N
    __shared__ int4   sb[N_];   // {base_top, base_bot, s0|(s1<<8), valid}

    int bq  = blockIdx.x;       // 0..1799
    int b   = bq / Q_;
    int q   = bq % Q_;
    int tid = threadIdx.x;      // 0..63

    if (tid < N_) {
        int n = tid;
        const float* rp = ref_pts + ((size_t)b * Q_ + q) * 3;
        float px = rp[0], py = rp[1], pz = rp[2];

        const float* M = lidar2img + ((size_t)b * N_ + n) * 16;
        float xc = M[0]  * px + M[1]  * py + M[2]  * pz + M[3];
        float yc = M[4]  * px + M[5]  * py + M[6]  * pz + M[7];
        float zc = M[8]  * px + M[9]  * py + M[10] * pz + M[11];

        float denom = fabsf(zc) + EPS_;
        float x2d = xc / denom;
        float y2d = yc / denom;

        float gx = x2d / (float)(W_ - 1) * 2.0f - 1.0f;
        float gy = y2d / (float)(H_ - 1) * 2.0f - 1.0f;

        bool front  = zc > EPS_;
        bool in_img = fmaxf(fabsf(gx), fabsf(gy)) <= 1.0f;
        int  valid  = (front && in_img) ? 1 : 0;
        float vv    = valid ? (1.0f / (float)N_) : 0.0f;

        float x = ((gx + 1.0f) * (float)W_ - 1.0f) * 0.5f;
        float y = ((gy + 1.0f) * (float)H_ - 1.0f) * 0.5f;
        x = fminf(fmaxf(x, -100.0f), (float)(W_ + 100));
        y = fminf(fmaxf(y, -100.0f), (float)(H_ + 100));

        float x0f = floorf(x), y0f = floorf(y);
        float wx = x - x0f, wy = y - y0f;
        int x0 = (int)x0f, y0 = (int)y0f;
        int x1 = x0 + 1,   y1 = y0 + 1;

        float v00 = (x0 >= 0 && x0 < W_ && y0 >= 0 && y0 < H_) ? 1.0f : 0.0f;
        float v10 = (x1 >= 0 && x1 < W_ && y0 >= 0 && y0 < H_) ? 1.0f : 0.0f;
        float v01 = (x0 >= 0 && x0 < W_ && y1 >= 0 && y1 < H_) ? 1.0f : 0.0f;
        float v11 = (x1 >= 0 && x1 < W_ && y1 >= 0 && y1 < H_) ? 1.0f : 0.0f;

        float4 w;
        w.x = (1.0f - wx) * (1.0f - wy) * v00 * vv;
        w.y = wx          * (1.0f - wy) * v10 * vv;
        w.z = (1.0f - wx) * wy          * v01 * vv;
        w.w = wx          * wy          * v11 * vv;

        int cx0 = min(max(x0, 0), W_ - 1);
        int cx1 = min(max(x1, 0), W_ - 1);
        int cy0 = min(max(y0, 0), H_ - 1);
        int cy1 = min(max(y1, 0), H_ - 1);

        int i0 = cy0 * W_ + cx0;
        int i1 = cy0 * W_ + cx1;
        int j0 = cy1 * W_ + cx0;

        int base_t = i0 & ~3;
        int s0 = i0 - base_t;
        int s1 = i1 - base_t;
        int base_b = j0 - s0;

        sw[n] = w;
        sb[n] = make_int4(base_t, base_b, s0 | (s1 << 8), valid);
    }
    __syncthreads();

    float acc0 = 0.0f;   // channel tid
    float acc1 = 0.0f;   // channel tid + 64
    float acc2 = 0.0f;   // channel tid + 128
    float acc3 = 0.0f;   // channel tid + 192
#pragma unroll
    for (int n = 0; n < N_; n++) {
        int4 ib = sb[n];
        if (!ib.w) continue;            // uniform branch: camera invalid
        float4 w = sw[n];
        const float* p0 = feats + ((size_t)((b * N_ + n) * C_) + tid) * HW_;
        const float* p1 = p0 + (size_t)64  * HW_;
        const float* p2 = p0 + (size_t)128 * HW_;
        const float* p3 = p0 + (size_t)192 * HW_;

        // issue all 8 independent 16B loads before consuming
        float4 t0 = *reinterpret_cast<const float4*>(p0 + ib.x);
        float4 b0v = *reinterpret_cast<const float4*>(p0 + ib.y);
        float4 t1 = *reinterpret_cast<const float4*>(p1 + ib.x);
        float4 b1v = *reinterpret_cast<const float4*>(p1 + ib.y);
        float4 t2 = *reinterpret_cast<const float4*>(p2 + ib.x);
        float4 b2v = *reinterpret_cast<const float4*>(p2 + ib.y);
        float4 t3 = *reinterpret_cast<const float4*>(p3 + ib.x);
        float4 b3v = *reinterpret_cast<const float4*>(p3 + ib.y);

        int s0 = ib.z & 0xff;
        int s1 = ib.z >> 8;

        float vt0a = sel4(t0, s0), vb0a = sel4(b0v, s0);
        float vt0b = sel4(t1, s0), vb0b = sel4(b1v, s0);
        float vt0c = sel4(t2, s0), vb0c = sel4(b2v, s0);
        float vt0d = sel4(t3, s0), vb0d = sel4(b3v, s0);
        float vt1a, vb1a, vt1b, vb1b, vt1c, vb1c, vt1d, vb1d;
        if (s1 < 4) {                   // uniform branch (75% taken)
            vt1a = sel4(t0, s1);  vb1a = sel4(b0v, s1);
            vt1b = sel4(t1, s1);  vb1b = sel4(b1v, s1);
            vt1c = sel4(t2, s1);  vb1c = sel4(b2v, s1);
            vt1d = sel4(t3, s1);  vb1d = sel4(b3v, s1);
        } else {                        // right pixel spills into next float4
            vt1a = __ldg(p0 + ib.x + 4);  vb1a = __ldg(p0 + ib.y + 4);
            vt1b = __ldg(p1 + ib.x + 4);  vb1b = __ldg(p1 + ib.y + 4);
            vt1c = __ldg(p2 + ib.x + 4);  vb1c = __ldg(p2 + ib.y + 4);
            vt1d = __ldg(p3 + ib.x + 4);  vb1d = __ldg(p3 + ib.y + 4);
        }
        acc0 = fmaf(w.x, vt0a, acc0);
        acc0 = fmaf(w.y, vt1a, acc0);
        acc0 = fmaf(w.z, vb0a, acc0);
        acc0 = fmaf(w.w, vb1a, acc0);
        acc1 = fmaf(w.x, vt0b, acc1);
        acc1 = fmaf(w.y, vt1b, acc1);
        acc1 = fmaf(w.z, vb0b, acc1);
        acc1 = fmaf(w.w, vb1b, acc1);
        acc2 = fmaf(w.x, vt0c, acc2);
        acc2 = fmaf(w.y, vt1c, acc2);
        acc2 = fmaf(w.z, vb0c, acc2);
        acc2 = fmaf(w.w, vb1c, acc2);
        acc3 = fmaf(w.x, vt0d, acc3);
        acc3 = fmaf(w.y, vt1d, acc3);
        acc3 = fmaf(w.z, vb0d, acc3);
        acc3 = fmaf(w.w, vb1d, acc3);
    }
    float* outp = &g_agg[(size_t)bq * C_ + tid];
    outp[0]   = acc0;
    outp[64]  = acc1;
    outp[128] = acc2;
    outp[192] = acc3;
}

// ---------------------------------------------------------------------------
// Split-K GEMM (KSPLIT=8): part[z] = agg[:, z*32:(z+1)*32] @ W^T[...]
// 64x64 tile, BK=16, 2 tiles per block, f32x2 packed FMAs,
// A duplicated in smem (broadcast -> conflict-free), B natural pairs.
// ---------------------------------------------------------------------------
#define BM 64
#define BN 64
#define BK 16
#define NT (KCHUNK / BK)   // 2 tiles per k-chunk

__global__ __launch_bounds__(256) void gemm_kernel(const float* __restrict__ Wm)
{
    __shared__ float AsDup[2][BK][BM * 2];   // 16 KB: each A value stored twice
    __shared__ float Bs[2][BK][BN];          // 8 KB

    const int M = BQ_;
    int t  = threadIdx.x;
    int tm = t / 16;
    int tn = t % 16;

    int bM = blockIdx.x * BM;
    int bN = blockIdx.y * BN;
    int z  = blockIdx.z;
    int kb = z * KCHUNK;

    int lrow = t >> 2;
    int lk   = (t & 3) * 4;

    const float* Aptr = &g_agg[(size_t)(bM + lrow) * C_ + kb + lk];
    const float* Bptr = &Wm[(size_t)(bN + lrow) * C_ + kb + lk];
    bool arow_ok = (bM + lrow) < M;

    unsigned long long acc2[4][2];
#pragma unroll
    for (int i = 0; i < 4; i++) { acc2[i][0] = 0ull; acc2[i][1] = 0ull; }

    float4 av = make_float4(0.f, 0.f, 0.f, 0.f);
    if (arow_ok) av = *reinterpret_cast<const float4*>(Aptr);
    float4 bv = *reinterpret_cast<const float4*>(Bptr);
    {
        float* ad = &AsDup[0][0][0];
        *reinterpret_cast<float2*>(&ad[(lk + 0) * (BM * 2) + lrow * 2]) = make_float2(av.x, av.x);
        *reinterpret_cast<float2*>(&ad[(lk + 1) * (BM * 2) + lrow * 2]) = make_float2(av.y, av.y);
        *reinterpret_cast<float2*>(&ad[(lk + 2) * (BM * 2) + lrow * 2]) = make_float2(av.z, av.z);
        *reinterpret_cast<float2*>(&ad[(lk + 3) * (BM * 2) + lrow * 2]) = make_float2(av.w, av.w);
        Bs[0][lk + 0][lrow] = bv.x;
        Bs[0][lk + 1][lrow] = bv.y;
        Bs[0][lk + 2][lrow] = bv.z;
        Bs[0][lk + 3][lrow] = bv.w;
    }
    __syncthreads();

#pragma unroll
    for (int tile = 0; tile < NT; tile++) {
        int cur = tile & 1;
        int nxt = cur ^ 1;

        if (tile + 1 < NT) {
            av = make_float4(0.f, 0.f, 0.f, 0.f);
            if (arow_ok) av = *reinterpret_cast<const float4*>(Aptr + (tile + 1) * BK);
            bv = *reinterpret_cast<const float4*>(Bptr + (tile + 1) * BK);
        }

        ulonglong2 fa01[2], fa23[2], fb[2];
        {
            const ulonglong2* ap = reinterpret_cast<const ulonglong2*>(&AsDup[cur][0][tm * 8]);
            fa01[0] = ap[0];
            fa23[0] = ap[1];
            fb[0]   = *reinterpret_cast<const ulonglong2*>(&Bs[cur][0][tn * 4]);
        }
#pragma unroll
        for (int kk = 0; kk < BK; kk++) {
            int c = kk & 1, nx = c ^ 1;
            if (kk + 1 < BK) {
                const ulonglong2* ap = reinterpret_cast<const ulonglong2*>(&AsDup[cur][kk + 1][tm * 8]);
                fa01[nx] = ap[0];
                fa23[nx] = ap[1];
                fb[nx]   = *reinterpret_cast<const ulonglong2*>(&Bs[cur][kk + 1][tn * 4]);
            }
            ffma2(acc2[0][0], fa01[c].x, fb[c].x);
            ffma2(acc2[0][1], fa01[c].x, fb[c].y);
            ffma2(acc2[1][0], fa01[c].y, fb[c].x);
            ffma2(acc2[1][1], fa01[c].y, fb[c].y);
            ffma2(acc2[2][0], fa23[c].x, fb[c].x);
            ffma2(acc2[2][1], fa23[c].x, fb[c].y);
            ffma2(acc2[3][0], fa23[c].y, fb[c].x);
            ffma2(acc2[3][1], fa23[c].y, fb[c].y);
        }

        if (tile + 1 < NT) {
            float* ad = &AsDup[nxt][0][0];
            *reinterpret_cast<float2*>(&ad[(lk + 0) * (BM * 2) + lrow * 2]) = make_float2(av.x, av.x);
            *reinterpret_cast<float2*>(&ad[(lk + 1) * (BM * 2) + lrow * 2]) = make_float2(av.y, av.y);
            *reinterpret_cast<float2*>(&ad[(lk + 2) * (BM * 2) + lrow * 2]) = make_float2(av.z, av.z);
            *reinterpret_cast<float2*>(&ad[(lk + 3) * (BM * 2) + lrow * 2]) = make_float2(av.w, av.w);
            Bs[nxt][lk + 0][lrow] = bv.x;
            Bs[nxt][lk + 1][lrow] = bv.y;
            Bs[nxt][lk + 2][lrow] = bv.z;
            Bs[nxt][lk + 3][lrow] = bv.w;
            __syncthreads();
        }
    }

    float* pout = &g_part[z][0];
#pragma unroll
    for (int i = 0; i < 4; i++) {
        int gm = bM + tm * 4 + i;
        if (gm >= M) continue;
        float2 lo = *reinterpret_cast<float2*>(&acc2[i][0]);
        float2 hi = *reinterpret_cast<float2*>(&acc2[i][1]);
        *reinterpret_cast<float4*>(&pout[(size_t)gm * C_ + bN + tn * 4]) =
            make_float4(lo.x, lo.y, hi.x, hi.y);
    }
}

// ---------------------------------------------------------------------------
// fixup: out = sum_z part[z] + bias    (fixed order -> deterministic)
// ---------------------------------------------------------------------------
__global__ __launch_bounds__(256) void fixup_kernel(const float* __restrict__ bias,
                                                    float* __restrict__ out)
{
    int i = blockIdx.x * blockDim.x + threadIdx.x;   // float4 index
    const int NV = BQ_ * C_ / 4;                     // 115200
    if (i >= NV) return;
    int e = i * 4;
    float4 s = *reinterpret_cast<const float4*>(&g_part[0][e]);
#pragma unroll
    for (int z = 1; z < KSPLIT; z++) {
        float4 p = *reinterpret_cast<const float4*>(&g_part[z][e]);
        s.x += p.x; s.y += p.y; s.z += p.z; s.w += p.w;
    }
    float4 bb = *reinterpret_cast<const float4*>(&bias[e & (C_ - 1)]);
    s.x += bb.x; s.y += bb.y; s.z += bb.z; s.w += bb.w;
    *reinterpret_cast<float4*>(&out[e]) = s;
}

// ---------------------------------------------------------------------------
// launch
// inputs: 0=query (unused), 1=reference_points, 2=image_features,
//         3=lidar2img, 4=W_out, 5=b_out; output float32 (B,Q,C)
// ---------------------------------------------------------------------------
extern "C" void kernel_launch(void* const* d_in, const int* in_sizes, int n_in,
                              void* d_out, int out_size)
{
    const float* ref_pts   = (const float*)d_in[1];
    const float* feats     = (const float*)d_in[2];
    const float* lidar2img = (const float*)d_in[3];
    const float* Wm        = (const float*)d_in[4];
    const float* bias      = (const float*)d_in[5];
    float* out = (float*)d_out;

    gather_kernel<<<BQ_, 64>>>(feats, ref_pts, lidar2img);
    dim3 gg((BQ_ + BM - 1) / BM, C_ / BN, KSPLIT);
    gemm_kernel<<<gg, 256>>>(Wm);
    fixup_kernel<<<(BQ_ * C_ / 4 + 255) / 256, 256>>>(bias, out);
}